// round 8
// baseline (speedup 1.0000x reference)
#include <cuda_runtime.h>
#include <cuda_bf16.h>
#include <stdint.h>
#include <math.h>

#define BATCH 256
#define SEQ   256
#define IDIM  128
#define HID   1024
#define OUTC  10

#define NCTA  128
#define NTH   256

// smem geometry (uint32 words)
#define BPLANE 136                 // B per-slot plane stride (136 % 32 == 8)
#define BGK    544                 // per-k16 B words (4 planes)
#define NBGK   72                  // 72 k16 groups (64 h + 8 x)
#define SBW    (NBGK * BGK)        // 39168 words
#define APLANE 264                 // A plane stride (264 % 32 == 8)
#define ABUF   (8 * APLANE)        // 2112 words per buffer
#define AGRP   (2 * ABUF)          // per K-group (double buffered)
#define DSMW   (SBW + 4 * AGRP)    // 56064 words
#define DSMB   (DSMW * 4)          // 224256 bytes

// -------- device globals --------
__device__ uint32_t g_xs[(long)BATCH * SEQ * 8 * 16];     // packed x slots
__device__ uint32_t g_bs[32L * NBGK * 4 * 32 * 4];        // packed W slabs (4.7MB)
__device__ uint32_t g_hs[2][BATCH * 64 * 16];             // packed h, double-buffered
__device__ unsigned int g_bar;

// -------- helpers --------
static __device__ __forceinline__ uint32_t pk2(float a, float b) {
    __nv_bfloat162 t = __floats2bfloat162_rn(a, b);
    return *reinterpret_cast<uint32_t*>(&t);
}
static __device__ __forceinline__ float bf16rt(float v) {
    return __bfloat162float(__float2bfloat16_rn(v));
}
static __device__ __forceinline__ void mma16(float* c,
        uint32_t a0, uint32_t a1, uint32_t a2, uint32_t a3,
        uint32_t b0, uint32_t b1) {
    asm volatile(
        "mma.sync.aligned.m16n8k16.row.col.f32.bf16.bf16.f32 "
        "{%0,%1,%2,%3},{%4,%5,%6,%7},{%8,%9},{%0,%1,%2,%3};"
        : "+f"(c[0]), "+f"(c[1]), "+f"(c[2]), "+f"(c[3])
        : "r"(a0), "r"(a1), "r"(a2), "r"(a3), "r"(b0), "r"(b1));
}
static __device__ __forceinline__ float my_tanh(float v) {
    float e = __expf(2.0f * v);
    return 1.0f - 2.0f / (e + 1.0f);
}
static __device__ __forceinline__ void grid_sync() {
    __syncthreads();
    if (threadIdx.x == 0) {
        __threadfence();
        unsigned ticket = atomicAdd(&g_bar, 1u);
        unsigned target = (ticket / NCTA + 1u) * NCTA;
        volatile unsigned* p = &g_bar;
        while (*p < target) { }
    }
    __syncthreads();
    __threadfence();
}
// slot packer: v[16] -> 4 uint4 slots, slot t = {hi(2t,2t+1), hi(2t+8,2t+9), lo.., lo..}
static __device__ __forceinline__ void pack16(const float* v, uint4* dst) {
    #pragma unroll
    for (int t = 0; t < 4; t++) {
        const float a0 = v[2*t],   a1 = v[2*t+1];
        const float a8 = v[2*t+8], a9 = v[2*t+9];
        uint4 s;
        s.x = pk2(a0, a1);
        s.y = pk2(a8, a9);
        s.z = pk2(a0 - bf16rt(a0), a1 - bf16rt(a1));
        s.w = pk2(a8 - bf16rt(a8), a9 - bf16rt(a9));
        dst[t] = s;
    }
}

// -------- prep --------
__global__ void prep_kernel(const float* __restrict__ x,
                            const float* __restrict__ Whx,
                            const float* __restrict__ Whh) {
    const long tid = (long)blockIdx.x * blockDim.x + threadIdx.x;
    const long nt  = (long)gridDim.x * blockDim.x;
    // x: per (b*t, g16)
    for (long i = tid; i < (long)BATCH * SEQ * 8; i += nt) {
        const long bt = i >> 3;
        const int  g  = (int)(i & 7);
        const float* src = x + bt * IDIM + g * 16;
        float v[16];
        #pragma unroll
        for (int j = 0; j < 16; j++) v[j] = src[j];
        pack16(v, (uint4*)(g_xs + i * 16));
    }
    // W: per (tn, gk, t, col) -> one uint4
    for (long i = tid; i < 32L * NBGK * 4 * 32; i += nt) {
        const int col = (int)(i & 31);
        const int t   = (int)((i >> 5) & 3);
        long rest = i >> 7;
        const int gk = (int)(rest % NBGK);
        const int tn = (int)(rest / NBGK);
        const int n  = tn * 32 + col;
        float w[4];
        #pragma unroll
        for (int j = 0; j < 4; j++) {
            const int kk = ((j & 1) ? 1 : 0) + ((j >> 1) ? 8 : 0) + 2 * t; // 2t,2t+1,2t+8,2t+9
            float val;
            if (gk < 64) {
                const int k = gk * 16 + kk;
                val = Whh[(long)k * HID + n];
            } else {
                const int k = (gk - 64) * 16 + kk;
                val = Whx[(long)k * HID + n];
            }
            w[j] = val;
        }
        uint4 s;
        s.x = pk2(w[0], w[1]);
        s.y = pk2(w[2], w[3]);
        s.z = pk2(w[0] - bf16rt(w[0]), w[1] - bf16rt(w[1]));
        s.w = pk2(w[2] - bf16rt(w[2]), w[3] - bf16rt(w[3]));
        ((uint4*)g_bs)[i] = s;
    }
    // zero h0 (parity 0)
    for (long i = tid; i < (long)BATCH * 64 * 16; i += nt) g_hs[0][i] = 0u;
}

// -------- main persistent kernel --------
__global__ void __launch_bounds__(NTH, 1)
rnn_kernel(const float* __restrict__ bh,
           const float* __restrict__ Why,
           const float* __restrict__ bo,
           float* __restrict__ out) {
    extern __shared__ uint32_t dsm[];
    uint32_t* sB = dsm;           // resident B slab
    uint32_t* sA = dsm + SBW;     // 4 groups x 2 buffers
    __shared__ float sBias[32];
    __shared__ float red[8][OUTC];

    const int tid  = threadIdx.x;
    const int bid  = blockIdx.x;
    const int wid  = tid >> 5;
    const int lane = tid & 31;

    const int tileM = bid & 3;
    const int tileN = bid >> 2;
    const int m0 = tileM * 64;
    const int n0 = tileN * 32;

    const int kg  = wid >> 1;      // K-group 0..3
    const int qm  = wid & 1;       // row half of 64
    const int grp = lane >> 2;
    const int tig = lane & 3;
    const int ltid = tid & 63;     // row within group staging

    // ---- preload resident B slab ----
    {
        const uint4* bsrc = (const uint4*)g_bs + (long)tileN * (NBGK * 4 * 32);
        for (int i = tid; i < NBGK * 4 * 32; i += NTH) {
            const int gk = i >> 7;
            const int t  = (i >> 5) & 3;
            const int col = i & 31;
            *(uint4*)(sB + gk * BGK + t * BPLANE + col * 4) = bsrc[i];
        }
    }
    if (tid < 32) sBias[tid] = bh[n0 + tid];
    __syncthreads();

    uint32_t* myA = sA + kg * AGRP;
    float acc[2][4][4];
    uint4 u[8];

    for (int t = 0; t < SEQ; t++) {
        #pragma unroll
        for (int mt = 0; mt < 2; mt++)
            #pragma unroll
            for (int nt = 0; nt < 4; nt++)
                #pragma unroll
                for (int c = 0; c < 4; c++)
                    acc[mt][nt][c] = 0.f;

        // ======== x chunk (h-independent), before grid sync ========
        {
            const uint32_t* src = g_xs + (((long)(m0 + ltid) * SEQ + t) * 8 + kg * 2) * 16;
            #pragma unroll
            for (int w = 0; w < 8; w++) u[w] = ((const uint4*)src)[w];
            #pragma unroll
            for (int w = 0; w < 8; w++)
                *(uint4*)(myA + w * APLANE + ltid * 4) = u[w];
        }
        asm volatile("bar.sync %0, 64;" :: "r"(kg + 1) : "memory");
        {
            const int gk0 = 64 + kg * 2;
            #pragma unroll
            for (int s = 0; s < 2; s++) {
                uint4 ra[2][2];
                #pragma unroll
                for (int mt = 0; mt < 2; mt++)
                    #pragma unroll
                    for (int rh = 0; rh < 2; rh++) {
                        const int row = qm * 32 + mt * 16 + rh * 8 + grp;
                        ra[mt][rh] = *(const uint4*)(myA + (s * 4 + tig) * APLANE + row * 4);
                    }
                const uint32_t* bq = sB + (gk0 + s) * BGK + tig * BPLANE;
                #pragma unroll
                for (int nt = 0; nt < 4; nt++) {
                    const uint4 bv = *(const uint4*)(bq + (nt * 8 + grp) * 4);
                    #pragma unroll
                    for (int mt = 0; mt < 2; mt++) {
                        mma16(acc[mt][nt], ra[mt][0].x, ra[mt][1].x, ra[mt][0].y, ra[mt][1].y, bv.x, bv.y);
                        mma16(acc[mt][nt], ra[mt][0].x, ra[mt][1].x, ra[mt][0].y, ra[mt][1].y, bv.z, bv.w);
                        mma16(acc[mt][nt], ra[mt][0].z, ra[mt][1].z, ra[mt][0].w, ra[mt][1].w, bv.x, bv.y);
                    }
                }
            }
        }

        grid_sync();   // h_t (written by previous step's epilogue) now visible

        // ======== 8 h chunks (k32 each), double-buffered ========
        const uint32_t* hbase = g_hs[t & 1];
        {
            const uint32_t* src = hbase + ((long)(m0 + ltid) * 64 + kg * 16) * 16;
            #pragma unroll
            for (int w = 0; w < 8; w++) u[w] = ((const uint4*)src)[w];
            uint32_t* dst = myA + ABUF;   // buf1
            #pragma unroll
            for (int w = 0; w < 8; w++)
                *(uint4*)(dst + w * APLANE + ltid * 4) = u[w];
        }
        asm volatile("bar.sync %0, 64;" :: "r"(kg + 1) : "memory");

        #pragma unroll 1
        for (int c = 0; c < 8; c++) {
            if (c < 7) {
                const uint32_t* src = hbase +
                    ((long)(m0 + ltid) * 64 + kg * 16 + (c + 1) * 2) * 16;
                #pragma unroll
                for (int w = 0; w < 8; w++) u[w] = ((const uint4*)src)[w];
            }
            // compute chunk c from buffer (c+1)&1
            {
                uint32_t* ab = myA + ((c + 1) & 1) * ABUF;
                const int gk0 = kg * 16 + c * 2;
                #pragma unroll
                for (int s = 0; s < 2; s++) {
                    uint4 ra[2][2];
                    #pragma unroll
                    for (int mt = 0; mt < 2; mt++)
                        #pragma unroll
                        for (int rh = 0; rh < 2; rh++) {
                            const int row = qm * 32 + mt * 16 + rh * 8 + grp;
                            ra[mt][rh] = *(const uint4*)(ab + (s * 4 + tig) * APLANE + row * 4);
                        }
                    const uint32_t* bq = sB + (gk0 + s) * BGK + tig * BPLANE;
                    #pragma unroll
                    for (int nt = 0; nt < 4; nt++) {
                        const uint4 bv = *(const uint4*)(bq + (nt * 8 + grp) * 4);
                        #pragma unroll
                        for (int mt = 0; mt < 2; mt++) {
                            mma16(acc[mt][nt], ra[mt][0].x, ra[mt][1].x, ra[mt][0].y, ra[mt][1].y, bv.x, bv.y);
                            mma16(acc[mt][nt], ra[mt][0].x, ra[mt][1].x, ra[mt][0].y, ra[mt][1].y, bv.z, bv.w);
                            mma16(acc[mt][nt], ra[mt][0].z, ra[mt][1].z, ra[mt][0].w, ra[mt][1].w, bv.x, bv.y);
                        }
                    }
                }
            }
            if (c < 7) {
                uint32_t* dst = myA + (c & 1) * ABUF;
                #pragma unroll
                for (int w = 0; w < 8; w++)
                    *(uint4*)(dst + w * APLANE + ltid * 4) = u[w];
            }
            asm volatile("bar.sync %0, 64;" :: "r"(kg + 1) : "memory");
        }

        // ======== epilogue: intra-CTA K-combine + tanh + pack + store ========
        // each group writes its partial tile into its buf1 region, [64][33] floats
        {
            float* comb = (float*)(myA + ABUF);
            #pragma unroll
            for (int mt = 0; mt < 2; mt++) {
                const int row = qm * 32 + mt * 16 + grp;
                #pragma unroll
                for (int nt = 0; nt < 4; nt++) {
                    const int col = nt * 8 + tig * 2;
                    comb[row * 33 + col]           = acc[mt][nt][0];
                    comb[row * 33 + col + 1]       = acc[mt][nt][1];
                    comb[(row + 8) * 33 + col]     = acc[mt][nt][2];
                    comb[(row + 8) * 33 + col + 1] = acc[mt][nt][3];
                }
            }
        }
        __syncthreads();
        {
            uint32_t* hdst = g_hs[(t + 1) & 1];
            #pragma unroll
            for (int j = 0; j < 2; j++) {
                const int task  = tid + j * 256;
                const int row   = task >> 3;
                const int g16   = (task >> 2) & 1;
                const int tslot = task & 3;
                const int c0 = g16 * 16 + 2 * tslot;
                const int c2 = c0 + 8;
                float v0 = 0.f, v1 = 0.f, v2 = 0.f, v3 = 0.f;
                #pragma unroll
                for (int g = 0; g < 4; g++) {
                    const float* cb = (const float*)(sA + g * AGRP + ABUF);
                    v0 += cb[row * 33 + c0];
                    v1 += cb[row * 33 + c0 + 1];
                    v2 += cb[row * 33 + c2];
                    v3 += cb[row * 33 + c2 + 1];
                }
                const float t0 = my_tanh(v0 + sBias[c0]);
                const float t1 = my_tanh(v1 + sBias[c0 + 1]);
                const float t2 = my_tanh(v2 + sBias[c2]);
                const float t3 = my_tanh(v3 + sBias[c2 + 1]);
                uint4 s;
                s.x = pk2(t0, t1);
                s.y = pk2(t2, t3);
                s.z = pk2(t0 - bf16rt(t0), t1 - bf16rt(t1));
                s.w = pk2(t2 - bf16rt(t2), t3 - bf16rt(t3));
                *(uint4*)(hdst + ((long)(m0 + row) * 64 + tileN * 2 + g16) * 16 + tslot * 4) = s;
            }
        }
        // no trailing sync: next step's grid_sync provides cross-CTA visibility;
        // next x-staging targets buf0 (combine lives in buf1), and h-staging of
        // buf1 happens only after the next grid_sync (all threads past epilogue).
    }

    grid_sync();   // final h (parity 0) visible

    // ======== classifier + softmax: 2 rows per CTA ========
    for (int rr = 0; rr < 2; rr++) {
        const int row = bid * 2 + rr;
        const uint32_t* hrow = g_hs[0] + (long)row * 64 * 16;
        float a[OUTC];
        #pragma unroll
        for (int o = 0; o < OUTC; o++) a[o] = 0.f;
        {
            const int gk = tid >> 2;
            const int ts = tid & 3;
            const uint4 v = *(const uint4*)(hrow + gk * 16 + ts * 4);
            const __nv_bfloat162 h01 = *(const __nv_bfloat162*)&v.x;
            const __nv_bfloat162 h23 = *(const __nv_bfloat162*)&v.y;
            const __nv_bfloat162 l01 = *(const __nv_bfloat162*)&v.z;
            const __nv_bfloat162 l23 = *(const __nv_bfloat162*)&v.w;
            const float hv0 = __bfloat162float(h01.x) + __bfloat162float(l01.x);
            const float hv1 = __bfloat162float(h01.y) + __bfloat162float(l01.y);
            const float hv2 = __bfloat162float(h23.x) + __bfloat162float(l23.x);
            const float hv3 = __bfloat162float(h23.y) + __bfloat162float(l23.y);
            const int k0 = gk * 16 + 2 * ts;
            const int k2 = k0 + 8;
            #pragma unroll
            for (int o = 0; o < OUTC; o++)
                a[o] += hv0 * Why[(long)k0 * OUTC + o] + hv1 * Why[(long)(k0 + 1) * OUTC + o]
                      + hv2 * Why[(long)k2 * OUTC + o] + hv3 * Why[(long)(k2 + 1) * OUTC + o];
        }
        #pragma unroll
        for (int o = 0; o < OUTC; o++)
            #pragma unroll
            for (int off = 16; off > 0; off >>= 1)
                a[o] += __shfl_down_sync(0xffffffffu, a[o], off);
        if (lane == 0) {
            #pragma unroll
            for (int o = 0; o < OUTC; o++) red[wid][o] = a[o];
        }
        __syncthreads();
        if (tid == 0) {
            float v[OUTC];
            float mx = -1e30f;
            #pragma unroll
            for (int o = 0; o < OUTC; o++) {
                float s8 = 0.f;
                #pragma unroll
                for (int w = 0; w < 8; w++) s8 += red[w][o];
                v[o] = s8 + bo[o];
                mx = fmaxf(mx, v[o]);
            }
            float s = 0.f;
            #pragma unroll
            for (int o = 0; o < OUTC; o++) { v[o] = expf(v[o] - mx); s += v[o]; }
            const float inv = 1.0f / s;
            #pragma unroll
            for (int o = 0; o < OUTC; o++) out[row * OUTC + o] = v[o] * inv;
        }
        __syncthreads();
    }
}

extern "C" void kernel_launch(void* const* d_in, const int* in_sizes, int n_in,
                              void* d_out, int out_size) {
    const float* x   = (const float*)d_in[0];
    const float* Whx = (const float*)d_in[1];
    const float* Whh = (const float*)d_in[2];
    const float* bh  = (const float*)d_in[3];
    const float* Why = (const float*)d_in[4];
    const float* bo  = (const float*)d_in[5];
    float* out = (float*)d_out;

    static int attr_done = 0;
    if (!attr_done) {
        cudaFuncSetAttribute(rnn_kernel,
                             cudaFuncAttributeMaxDynamicSharedMemorySize,
                             DSMB);
        attr_done = 1;
    }
    prep_kernel<<<1024, 256>>>(x, Whx, Whh);
    rnn_kernel<<<NCTA, NTH, DSMB>>>(bh, Why, bo, out);
}

// round 9
// speedup vs baseline: 1.4695x; 1.4695x over previous
#include <cuda_runtime.h>
#include <cuda_bf16.h>
#include <stdint.h>
#include <math.h>

#define BATCH 256
#define SEQ   256
#define IDIM  128
#define HID   1024
#define OUTC  10

#define NCTA  128
#define NTH   256
#define NSETS 2
#define SETC  64              // CTAs per independent set
#define CHW   2048            // uint32 words per k16 tile (128 rows * 16)
#define NBGK  9               // B k16-groups per CTA (1 x + 8 h)
#define SBW   (NBGK * CHW)    // 18432 words (72KB)
#define SAW   (2 * 2 * CHW)   // A: 2 bufs x 2 subs (32KB)
#define DSMW  (SBW + SAW)
#define DSMB  (DSMW * 4)      // 106496 bytes

// -------- device globals --------
__device__ uint32_t g_xs[(long)BATCH * SEQ * 8 * 16];    // packed x slots
__device__ uint32_t g_bs[8L * 8 * NBGK * 128 * 16];      // packed W slabs (4.5MB)
__device__ uint32_t g_hs[BATCH * 64 * 16];               // packed h slots (1MB)
__device__ float    g_h[BATCH * HID];                    // plain h (final step)
__device__ float4   g_part[NCTA * 8 * 16 * 32];          // partials (8MB)
__device__ unsigned int g_bar[NSETS * 32];               // per-set counters, padded

// -------- helpers --------
static __device__ __forceinline__ uint32_t pk2(float a, float b) {
    __nv_bfloat162 t = __floats2bfloat162_rn(a, b);
    return *reinterpret_cast<uint32_t*>(&t);
}
static __device__ __forceinline__ float bf16rt(float v) {
    return __bfloat162float(__float2bfloat16_rn(v));
}
static __device__ __forceinline__ void mma16(float* c,
        uint32_t a0, uint32_t a1, uint32_t a2, uint32_t a3,
        uint32_t b0, uint32_t b1) {
    asm volatile(
        "mma.sync.aligned.m16n8k16.row.col.f32.bf16.bf16.f32 "
        "{%0,%1,%2,%3},{%4,%5,%6,%7},{%8,%9},{%0,%1,%2,%3};"
        : "+f"(c[0]), "+f"(c[1]), "+f"(c[2]), "+f"(c[3])
        : "r"(a0), "r"(a1), "r"(a2), "r"(a3), "r"(b0), "r"(b1));
}
static __device__ __forceinline__ float my_tanh(float v) {
    float e = __expf(2.0f * v);
    return 1.0f - 2.0f / (e + 1.0f);
}
// per-set grid barrier (monotonic ticket; survives graph replays)
static __device__ __forceinline__ void set_sync(int set) {
    __syncthreads();
    if (threadIdx.x == 0) {
        __threadfence();
        unsigned* ctr = &g_bar[set * 32];
        unsigned ticket = atomicAdd(ctr, 1u);
        unsigned target = (ticket / SETC + 1u) * SETC;
        volatile unsigned* p = ctr;
        while (*p < target) { }
    }
    __syncthreads();
    __threadfence();
}
// slot packer: v[16] -> 4 uint4 slots
static __device__ __forceinline__ void pack16(const float* v, uint4* dst) {
    #pragma unroll
    for (int t = 0; t < 4; t++) {
        const float a0 = v[2*t],   a1 = v[2*t+1];
        const float a8 = v[2*t+8], a9 = v[2*t+9];
        uint4 s;
        s.x = pk2(a0, a1);
        s.y = pk2(a8, a9);
        s.z = pk2(a0 - bf16rt(a0), a1 - bf16rt(a1));
        s.w = pk2(a8 - bf16rt(a8), a9 - bf16rt(a9));
        dst[t] = s;
    }
}

// -------- prep (same as R7) --------
__global__ void prep_kernel(const float* __restrict__ x,
                            const float* __restrict__ Whx,
                            const float* __restrict__ Whh) {
    const long tid = (long)blockIdx.x * blockDim.x + threadIdx.x;
    const long nt  = (long)gridDim.x * blockDim.x;
    for (long i = tid; i < (long)BATCH * SEQ * 8; i += nt) {
        const long bt = i >> 3;
        const int  g  = (int)(i & 7);
        const float* src = x + bt * IDIM + g * 16;
        float v[16];
        #pragma unroll
        for (int j = 0; j < 16; j++) v[j] = src[j];
        pack16(v, (uint4*)(g_xs + i * 16));
    }
    for (long i = tid; i < 8L * 8 * NBGK * 128; i += nt) {
        const int col = (int)(i & 127);
        long tmp = i >> 7;
        const int c  = (int)(tmp % NBGK); tmp /= NBGK;
        const int ks = (int)(tmp & 7);
        const int tn = (int)(tmp >> 3);
        const int n  = tn * 128 + col;
        const int kbase = (c == 0) ? (HID + ks * 16) : (ks * 128 + (c - 1) * 16);
        float v[16];
        #pragma unroll
        for (int j = 0; j < 16; j++) {
            const int k = kbase + j;
            v[j] = (k < HID) ? Whh[(long)k * HID + n] : Whx[(long)(k - HID) * HID + n];
        }
        pack16(v, (uint4*)(g_bs + i * 16));
    }
    for (long i = tid; i < (long)BATCH * 64 * 16; i += nt) g_hs[i] = 0u;
    for (long i = tid; i < (long)BATCH * HID; i += nt)     g_h[i]  = 0.f;
}

// -------- main persistent kernel --------
__global__ void __launch_bounds__(NTH, 1)
rnn_kernel(const float* __restrict__ bh,
           const float* __restrict__ Why,
           const float* __restrict__ bo,
           float* __restrict__ out) {
    extern __shared__ uint32_t dsm[];
    uint32_t* sB = dsm;            // resident B slab: [gk][row][16]
    uint32_t* sA = dsm + SBW;      // [buf][sub][row][16]
    __shared__ float red[8][OUTC];

    const int tid  = threadIdx.x;
    const int bid  = blockIdx.x;
    const int wid  = tid >> 5;
    const int lane = tid & 31;

    const int set   = bid >> 6;          // independent batch-half
    const int sbid  = bid & 63;
    const int tileN = sbid >> 3;
    const int ks    = sbid & 7;
    const int m0    = set * 128;
    const int n0    = tileN * 128;

    const int wm  = wid >> 2;
    const int wn  = wid & 3;
    const int grp = lane >> 2;
    const int tig = lane & 3;

    // staging lanes: 2 threads per row
    const int rrow = tid >> 1;
    const int half = tid & 1;

    // fragment smem offsets (words)
    const int aoff = (wm * 64 + grp) * 16 + tig * 4;
    const int boff = (wn * 32 + grp) * 16 + tig * 4;

    // ---- preload resident B slab ----
    {
        const uint4* bsrc = (const uint4*)g_bs + (long)(tileN * 8 + ks) * (NBGK * 512);
        uint4* dst = (uint4*)sB;
        for (int i = tid; i < NBGK * 512; i += NTH) dst[i] = bsrc[i];
    }
    __syncthreads();

    // reduce-phase constants
    int   r_m[2], r_n[2], r_hoff[2];
    long  r_pbase[2];
    float r_b0[2], r_b1[2];
    #pragma unroll
    for (int it = 0; it < 2; it++) {
        const int p  = ks * 16 + wid + it * 8;
        const int w  = p >> 4;
        const int qq = p & 15;
        const int wm_ = w >> 2, wn_ = w & 3;
        const int mt = qq >> 2, nt = qq & 3;
        r_m[it] = m0 + wm_ * 64 + mt * 16 + (lane >> 2);
        r_n[it] = n0 + wn_ * 32 + nt * 8 + (lane & 3) * 2;
        r_pbase[it] = ((long)(set * 64 + tileN * 8) * 8 + w) * 16 + qq;
        r_b0[it] = bh[r_n[it]];
        r_b1[it] = bh[r_n[it] + 1];
        const int j = r_n[it] & 15;
        r_hoff[it] = (r_m[it] * 64 + (r_n[it] >> 4)) * 16 +
                     ((j < 8) ? (j >> 1) * 4 : ((j - 8) >> 1) * 4 + 1);
    }

    float acc[4][4][4];
    uint4 u[4];

    // compute one k16 group: B group gk, A tile at `ab`
    auto compute16 = [&](int gk, const uint32_t* ab) {
        uint4 ra[4][2];
        const uint32_t* ap = ab + aoff;
        #pragma unroll
        for (int mt = 0; mt < 4; mt++) {
            ra[mt][0] = *(const uint4*)(ap + mt * 256);
            ra[mt][1] = *(const uint4*)(ap + mt * 256 + 128);
        }
        const uint32_t* bb = sB + gk * CHW + boff;
        #pragma unroll
        for (int nt = 0; nt < 4; nt++) {
            const uint4 bv = *(const uint4*)(bb + nt * 128);
            #pragma unroll
            for (int mt = 0; mt < 4; mt++) {
                mma16(acc[mt][nt], ra[mt][0].x, ra[mt][1].x, ra[mt][0].y, ra[mt][1].y, bv.x, bv.y);
                mma16(acc[mt][nt], ra[mt][0].x, ra[mt][1].x, ra[mt][0].y, ra[mt][1].y, bv.z, bv.w);
                mma16(acc[mt][nt], ra[mt][0].z, ra[mt][1].z, ra[mt][0].w, ra[mt][1].w, bv.x, bv.y);
            }
        }
    };
    // h chunk i (k32): thread stages k16-group (2i+half) into sub `half`
    auto ldg_h = [&](int i) {
        const uint32_t* src = g_hs +
            ((long)(m0 + rrow) * 64 + ks * 8 + 2 * i + half) * 16;
        #pragma unroll
        for (int w = 0; w < 4; w++) u[w] = ((const uint4*)src)[w];
    };
    auto sts_h = [&](int buf) {
        uint4* d = (uint4*)(sA + buf * (2 * CHW) + half * CHW + rrow * 16);
        #pragma unroll
        for (int w = 0; w < 4; w++) d[w] = u[w];
    };

    for (int t = 0; t < SEQ; t++) {
        #pragma unroll
        for (int mt = 0; mt < 4; mt++)
            #pragma unroll
            for (int nt = 0; nt < 4; nt++)
                #pragma unroll
                for (int c = 0; c < 4; c++)
                    acc[mt][nt][c] = 0.f;

        // ---- x chunk (k16, h-independent): before the set barrier ----
        {
            const uint32_t* src = g_xs +
                (((long)(m0 + rrow) * SEQ + t) * 8 + ks) * 16 + half * 8;
            u[0] = ((const uint4*)src)[0];
            u[1] = ((const uint4*)src)[1];
            uint4* d = (uint4*)(sA + rrow * 16 + half * 8);   // buf0 sub0
            d[0] = u[0];
            d[1] = u[1];
        }
        __syncthreads();
        compute16(0, sA);

        set_sync(set);   // h_t (previous step's reduce) now visible in this set

        // ---- 4 h chunks (k32 each), double-buffered ----
        ldg_h(0);
        sts_h(1);
        __syncthreads();
        #pragma unroll 1
        for (int i = 0; i < 4; i++) {
            if (i < 3) ldg_h(i + 1);
            const uint32_t* ab = sA + (((i + 1) & 1) * 2) * CHW;
            compute16(1 + 2 * i,     ab);
            compute16(1 + 2 * i + 1, ab + CHW);
            if (i < 3) {
                sts_h(i & 1);
                __syncthreads();
            }
        }

        // ---- store partials ----
        {
            float4* pp = g_part + ((long)(bid * 8 + wid) * 16) * 32 + lane;
            #pragma unroll
            for (int mt = 0; mt < 4; mt++)
                #pragma unroll
                for (int nt = 0; nt < 4; nt++) {
                    const int q = mt * 4 + nt;
                    pp[q * 32] = make_float4(acc[mt][nt][0], acc[mt][nt][1],
                                             acc[mt][nt][2], acc[mt][nt][3]);
                }
        }
        set_sync(set);

        // ---- reduce: sum 8 K-splits, bias+tanh, write packed h ----
        #pragma unroll
        for (int it = 0; it < 2; it++) {
            float s0 = 0.f, s1 = 0.f, s2 = 0.f, s3 = 0.f;
            #pragma unroll
            for (int k2 = 0; k2 < 8; k2++) {
                float4 v = g_part[(r_pbase[it] + (long)k2 * 128) * 32 + lane];
                s0 += v.x; s1 += v.y; s2 += v.z; s3 += v.w;
            }
            const float t0 = my_tanh(s0 + r_b0[it]);
            const float t1 = my_tanh(s1 + r_b1[it]);
            const float t2 = my_tanh(s2 + r_b0[it]);
            const float t3 = my_tanh(s3 + r_b1[it]);
            const float f0 = bf16rt(t0), f1 = bf16rt(t1);
            const float f2 = bf16rt(t2), f3 = bf16rt(t3);
            g_hs[r_hoff[it]]            = pk2(t0, t1);
            g_hs[r_hoff[it] + 2]        = pk2(t0 - f0, t1 - f1);
            g_hs[r_hoff[it] + 8192]     = pk2(t2, t3);
            g_hs[r_hoff[it] + 8192 + 2] = pk2(t2 - f2, t3 - f3);
            if (t == SEQ - 1) {
                g_h[(long)r_m[it] * HID + r_n[it]]           = t0;
                g_h[(long)r_m[it] * HID + r_n[it] + 1]       = t1;
                g_h[(long)(r_m[it] + 8) * HID + r_n[it]]     = t2;
                g_h[(long)(r_m[it] + 8) * HID + r_n[it] + 1] = t3;
            }
        }
        // no trailing sync: next step's set_sync provides visibility; x staging
        // reuses buf0 whose last reader (chunk 3) finished before this set_sync.
    }

    set_sync(set);   // final h of this set visible to this set's CTAs

    // ---- classifier + softmax: 2 rows per CTA (rows belong to own set) ----
    for (int rr = 0; rr < 2; rr++) {
        const int row = bid * 2 + rr;
        float a[OUTC];
        #pragma unroll
        for (int o = 0; o < OUTC; o++) a[o] = 0.f;
        for (int k = tid; k < HID; k += NTH) {
            const float hv = g_h[(long)row * HID + k];
            const float* wr = Why + (long)k * OUTC;
            #pragma unroll
            for (int o = 0; o < OUTC; o++) a[o] += hv * wr[o];
        }
        #pragma unroll
        for (int o = 0; o < OUTC; o++)
            #pragma unroll
            for (int off = 16; off > 0; off >>= 1)
                a[o] += __shfl_down_sync(0xffffffffu, a[o], off);
        if (lane == 0) {
            #pragma unroll
            for (int o = 0; o < OUTC; o++) red[wid][o] = a[o];
        }
        __syncthreads();
        if (tid == 0) {
            float v[OUTC];
            float mx = -1e30f;
            #pragma unroll
            for (int o = 0; o < OUTC; o++) {
                float s8 = 0.f;
                #pragma unroll
                for (int w = 0; w < 8; w++) s8 += red[w][o];
                v[o] = s8 + bo[o];
                mx = fmaxf(mx, v[o]);
            }
            float s = 0.f;
            #pragma unroll
            for (int o = 0; o < OUTC; o++) { v[o] = expf(v[o] - mx); s += v[o]; }
            const float inv = 1.0f / s;
            #pragma unroll
            for (int o = 0; o < OUTC; o++) out[row * OUTC + o] = v[o] * inv;
        }
        __syncthreads();
    }
}

extern "C" void kernel_launch(void* const* d_in, const int* in_sizes, int n_in,
                              void* d_out, int out_size) {
    const float* x   = (const float*)d_in[0];
    const float* Whx = (const float*)d_in[1];
    const float* Whh = (const float*)d_in[2];
    const float* bh  = (const float*)d_in[3];
    const float* Why = (const float*)d_in[4];
    const float* bo  = (const float*)d_in[5];
    float* out = (float*)d_out;

    static int attr_done = 0;
    if (!attr_done) {
        cudaFuncSetAttribute(rnn_kernel,
                             cudaFuncAttributeMaxDynamicSharedMemorySize,
                             DSMB);
        attr_done = 1;
    }
    prep_kernel<<<1024, 256>>>(x, Whx, Whh);
    rnn_kernel<<<NCTA, NTH, DSMB>>>(bh, Why, bo, out);
}

// round 10
// speedup vs baseline: 1.4803x; 1.0074x over previous
#include <cuda_runtime.h>
#include <cuda_bf16.h>
#include <stdint.h>
#include <math.h>

#define BATCH 256
#define SEQ   256
#define IDIM  128
#define HID   1024
#define OUTC  10

#define NCTA  128
#define NTH   256
#define NSETS 2
#define SETC  64
#define CHW   2048            // uint32 words per k16 tile (128 rows * 16)
#define NBGK  9               // B k16-groups per CTA (1 x + 8 h)
#define SBW   (NBGK * CHW)    // 72KB
#define SAW   (2 * 2 * CHW)   // A: 2 bufs x 2 subs (32KB)
#define DSMW  (SBW + SAW)
#define DSMB  (DSMW * 4)

// -------- device globals --------
__device__ uint32_t g_xs[(long)BATCH * SEQ * 8 * 16];    // packed x slots
__device__ uint32_t g_bs[8L * 8 * NBGK * 128 * 16];      // packed W slabs
__device__ uint32_t g_hs[2][BATCH * 64 * 16];            // packed h, parity-buffered
__device__ float    g_h[BATCH * HID];                    // plain h (final step)
__device__ float4   g_part[2][NCTA * 8 * 16 * 32];       // partials, parity-buffered
__device__ unsigned int g_pdone[NSETS][8 * 32];          // per-(set,tile) partial counters
__device__ unsigned int g_hdone[NSETS][8 * 32];          // per-(set,tile) h counters

// -------- helpers --------
static __device__ __forceinline__ uint32_t pk2(float a, float b) {
    __nv_bfloat162 t = __floats2bfloat162_rn(a, b);
    return *reinterpret_cast<uint32_t*>(&t);
}
static __device__ __forceinline__ float bf16rt(float v) {
    return __bfloat162float(__float2bfloat16_rn(v));
}
static __device__ __forceinline__ void mma16(float* c,
        uint32_t a0, uint32_t a1, uint32_t a2, uint32_t a3,
        uint32_t b0, uint32_t b1) {
    asm volatile(
        "mma.sync.aligned.m16n8k16.row.col.f32.bf16.bf16.f32 "
        "{%0,%1,%2,%3},{%4,%5,%6,%7},{%8,%9},{%0,%1,%2,%3};"
        : "+f"(c[0]), "+f"(c[1]), "+f"(c[2]), "+f"(c[3])
        : "r"(a0), "r"(a1), "r"(a2), "r"(a3), "r"(b0), "r"(b1));
}
static __device__ __forceinline__ float my_tanh(float v) {
    float e = __expf(2.0f * v);
    return 1.0f - 2.0f / (e + 1.0f);
}
// slot packer: v[16] -> 4 uint4 slots
static __device__ __forceinline__ void pack16(const float* v, uint4* dst) {
    #pragma unroll
    for (int t = 0; t < 4; t++) {
        const float a0 = v[2*t],   a1 = v[2*t+1];
        const float a8 = v[2*t+8], a9 = v[2*t+9];
        uint4 s;
        s.x = pk2(a0, a1);
        s.y = pk2(a8, a9);
        s.z = pk2(a0 - bf16rt(a0), a1 - bf16rt(a1));
        s.w = pk2(a8 - bf16rt(a8), a9 - bf16rt(a9));
        dst[t] = s;
    }
}

// -------- prep --------
__global__ void prep_kernel(const float* __restrict__ x,
                            const float* __restrict__ Whx,
                            const float* __restrict__ Whh) {
    const long tid = (long)blockIdx.x * blockDim.x + threadIdx.x;
    const long nt  = (long)gridDim.x * blockDim.x;
    for (long i = tid; i < (long)BATCH * SEQ * 8; i += nt) {
        const long bt = i >> 3;
        const int  g  = (int)(i & 7);
        const float* src = x + bt * IDIM + g * 16;
        float v[16];
        #pragma unroll
        for (int j = 0; j < 16; j++) v[j] = src[j];
        pack16(v, (uint4*)(g_xs + i * 16));
    }
    for (long i = tid; i < 8L * 8 * NBGK * 128; i += nt) {
        const int col = (int)(i & 127);
        long tmp = i >> 7;
        const int c  = (int)(tmp % NBGK); tmp /= NBGK;
        const int ks = (int)(tmp & 7);
        const int tn = (int)(tmp >> 3);
        const int n  = tn * 128 + col;
        const int kbase = (c == 0) ? (HID + ks * 16) : (ks * 128 + (c - 1) * 16);
        float v[16];
        #pragma unroll
        for (int j = 0; j < 16; j++) {
            const int k = kbase + j;
            v[j] = (k < HID) ? Whh[(long)k * HID + n] : Whx[(long)(k - HID) * HID + n];
        }
        pack16(v, (uint4*)(g_bs + i * 16));
    }
    for (long i = tid; i < (long)BATCH * 64 * 16; i += nt) g_hs[0][i] = 0u;
    for (long i = tid; i < (long)BATCH * HID; i += nt)     g_h[i]  = 0.f;
    // reset sync counters every launch (graph-replay safe)
    if (tid < NSETS * 8 * 32) {
        g_pdone[tid / (8 * 32)][tid % (8 * 32)] = 0u;
        g_hdone[tid / (8 * 32)][tid % (8 * 32)] = 0u;
    }
}

// -------- main persistent kernel --------
__global__ void __launch_bounds__(NTH, 1)
rnn_kernel(const float* __restrict__ bh,
           const float* __restrict__ Why,
           const float* __restrict__ bo,
           float* __restrict__ out) {
    extern __shared__ uint32_t dsm[];
    uint32_t* sB = dsm;            // resident B slab: [gk][row][16]
    uint32_t* sA = dsm + SBW;      // [buf][sub][row][16]
    __shared__ float red[8][OUTC];

    const int tid  = threadIdx.x;
    const int bid  = blockIdx.x;
    const int wid  = tid >> 5;
    const int lane = tid & 31;

    const int set   = bid >> 6;
    const int sbid  = bid & 63;
    const int tileN = sbid >> 3;
    const int ks    = sbid & 7;
    const int m0    = set * 128;
    const int n0    = tileN * 128;

    const int wm  = wid >> 2;
    const int wn  = wid & 3;
    const int grp = lane >> 2;
    const int tig = lane & 3;

    const int rrow = tid >> 1;
    const int half = tid & 1;

    const int aoff = (wm * 64 + grp) * 16 + tig * 4;
    const int boff = (wn * 32 + grp) * 16 + tig * 4;

    // point-to-point counters
    unsigned int* my_pctr = &g_pdone[set][tileN * 32];   // my tile's partial counter
    unsigned int* my_hctr = &g_hdone[set][tileN * 32];   // my tile's h counter
    volatile unsigned int* dep_hctr = &g_hdone[set][ks * 32];  // h producer I consume

    // ---- preload resident B slab ----
    {
        const uint4* bsrc = (const uint4*)g_bs + (long)(tileN * 8 + ks) * (NBGK * 512);
        uint4* dst = (uint4*)sB;
        for (int i = tid; i < NBGK * 512; i += NTH) dst[i] = bsrc[i];
    }
    __syncthreads();

    // reduce-phase constants
    int   r_m[2], r_n[2], r_hoff[2];
    long  r_pbase[2];
    float r_b0[2], r_b1[2];
    #pragma unroll
    for (int it = 0; it < 2; it++) {
        const int p  = ks * 16 + wid + it * 8;
        const int w  = p >> 4;
        const int qq = p & 15;
        const int wm_ = w >> 2, wn_ = w & 3;
        const int mt = qq >> 2, nt = qq & 3;
        r_m[it] = m0 + wm_ * 64 + mt * 16 + (lane >> 2);
        r_n[it] = n0 + wn_ * 32 + nt * 8 + (lane & 3) * 2;
        r_pbase[it] = ((long)(set * 64 + tileN * 8) * 8 + w) * 16 + qq;
        r_b0[it] = bh[r_n[it]];
        r_b1[it] = bh[r_n[it] + 1];
        const int j = r_n[it] & 15;
        r_hoff[it] = (r_m[it] * 64 + (r_n[it] >> 4)) * 16 +
                     ((j < 8) ? (j >> 1) * 4 : ((j - 8) >> 1) * 4 + 1);
    }

    float acc[4][4][4];
    uint4 u[4];
    const uint32_t* hbase_cur;

    auto compute16 = [&](int gk, const uint32_t* ab) {
        uint4 ra[4][2];
        const uint32_t* ap = ab + aoff;
        #pragma unroll
        for (int mt = 0; mt < 4; mt++) {
            ra[mt][0] = *(const uint4*)(ap + mt * 256);
            ra[mt][1] = *(const uint4*)(ap + mt * 256 + 128);
        }
        const uint32_t* bb = sB + gk * CHW + boff;
        #pragma unroll
        for (int nt = 0; nt < 4; nt++) {
            const uint4 bv = *(const uint4*)(bb + nt * 128);
            #pragma unroll
            for (int mt = 0; mt < 4; mt++) {
                mma16(acc[mt][nt], ra[mt][0].x, ra[mt][1].x, ra[mt][0].y, ra[mt][1].y, bv.x, bv.y);
                mma16(acc[mt][nt], ra[mt][0].x, ra[mt][1].x, ra[mt][0].y, ra[mt][1].y, bv.z, bv.w);
                mma16(acc[mt][nt], ra[mt][0].z, ra[mt][1].z, ra[mt][0].w, ra[mt][1].w, bv.x, bv.y);
            }
        }
    };
    auto ldg_h = [&](int i) {
        const uint32_t* src = hbase_cur +
            ((long)(m0 + rrow) * 64 + ks * 8 + 2 * i + half) * 16;
        #pragma unroll
        for (int w = 0; w < 4; w++) u[w] = ((const uint4*)src)[w];
    };
    auto sts_h = [&](int buf) {
        uint4* d = (uint4*)(sA + buf * (2 * CHW) + half * CHW + rrow * 16);
        #pragma unroll
        for (int w = 0; w < 4; w++) d[w] = u[w];
    };

    for (int t = 0; t < SEQ; t++) {
        #pragma unroll
        for (int mt = 0; mt < 4; mt++)
            #pragma unroll
            for (int nt = 0; nt < 4; nt++)
                #pragma unroll
                for (int c = 0; c < 4; c++)
                    acc[mt][nt][c] = 0.f;

        // ---- x chunk (k16, h-independent) ----
        {
            const uint32_t* src = g_xs +
                (((long)(m0 + rrow) * SEQ + t) * 8 + ks) * 16 + half * 8;
            u[0] = ((const uint4*)src)[0];
            u[1] = ((const uint4*)src)[1];
            uint4* d = (uint4*)(sA + rrow * 16 + half * 8);   // buf0 sub0
            d[0] = u[0];
            d[1] = u[1];
        }
        __syncthreads();
        compute16(0, sA);

        // ---- wait: tile `ks` finished its reduce of step t-1 ----
        if (tid == 0) {
            const unsigned target = 8u * (unsigned)t;
            while (*dep_hctr < target) { }
        }
        __syncthreads();
        __threadfence();

        hbase_cur = g_hs[t & 1];

        // ---- 4 h chunks (k32 each), double-buffered ----
        ldg_h(0);
        sts_h(1);
        __syncthreads();
        #pragma unroll 1
        for (int i = 0; i < 4; i++) {
            if (i < 3) ldg_h(i + 1);
            const uint32_t* ab = sA + (((i + 1) & 1) * 2) * CHW;
            compute16(1 + 2 * i,     ab);
            compute16(1 + 2 * i + 1, ab + CHW);
            if (i < 3) {
                sts_h(i & 1);
                __syncthreads();
            }
        }

        // ---- store partials (parity t) + signal ----
        {
            float4* pp = g_part[t & 1] + ((long)(bid * 8 + wid) * 16) * 32 + lane;
            #pragma unroll
            for (int mt = 0; mt < 4; mt++)
                #pragma unroll
                for (int nt = 0; nt < 4; nt++) {
                    const int q = mt * 4 + nt;
                    pp[q * 32] = make_float4(acc[mt][nt][0], acc[mt][nt][1],
                                             acc[mt][nt][2], acc[mt][nt][3]);
                }
        }
        __syncthreads();
        if (tid == 0) {
            __threadfence();
            atomicAdd(my_pctr, 1u);
        }

        // ---- wait: my tile's 8 partials stored ----
        if (tid == 0) {
            const unsigned target = 8u * (unsigned)(t + 1);
            volatile unsigned int* p = my_pctr;
            while (*p < target) { }
        }
        __syncthreads();
        __threadfence();

        // ---- reduce: sum 8 K-splits, bias+tanh, write packed h (parity t+1) ----
        {
            const float4* pbuf = g_part[t & 1];
            uint32_t* hdst = g_hs[(t + 1) & 1];
            #pragma unroll
            for (int it = 0; it < 2; it++) {
                float s0 = 0.f, s1 = 0.f, s2 = 0.f, s3 = 0.f;
                #pragma unroll
                for (int k2 = 0; k2 < 8; k2++) {
                    float4 v = pbuf[(r_pbase[it] + (long)k2 * 128) * 32 + lane];
                    s0 += v.x; s1 += v.y; s2 += v.z; s3 += v.w;
                }
                const float t0 = my_tanh(s0 + r_b0[it]);
                const float t1 = my_tanh(s1 + r_b1[it]);
                const float t2 = my_tanh(s2 + r_b0[it]);
                const float t3 = my_tanh(s3 + r_b1[it]);
                const float f0 = bf16rt(t0), f1 = bf16rt(t1);
                const float f2 = bf16rt(t2), f3 = bf16rt(t3);
                hdst[r_hoff[it]]            = pk2(t0, t1);
                hdst[r_hoff[it] + 2]        = pk2(t0 - f0, t1 - f1);
                hdst[r_hoff[it] + 8192]     = pk2(t2, t3);
                hdst[r_hoff[it] + 8192 + 2] = pk2(t2 - f2, t3 - f3);
                if (t == SEQ - 1) {
                    g_h[(long)r_m[it] * HID + r_n[it]]           = t0;
                    g_h[(long)r_m[it] * HID + r_n[it] + 1]       = t1;
                    g_h[(long)(r_m[it] + 8) * HID + r_n[it]]     = t2;
                    g_h[(long)(r_m[it] + 8) * HID + r_n[it] + 1] = t3;
                }
            }
        }
        // ---- signal: my tile's h columns for step t+1 written ----
        __syncthreads();
        if (tid == 0) {
            __threadfence();
            atomicAdd(my_hctr, 1u);
        }
    }

    // ---- wait for all tiles of my set to finish final reduce ----
    if (tid < 8) {
        volatile unsigned int* p = &g_hdone[set][tid * 32];
        const unsigned target = 8u * (unsigned)SEQ;
        while (*p < target) { }
    }
    __syncthreads();
    __threadfence();

    // ---- classifier + softmax: 2 rows per CTA ----
    for (int rr = 0; rr < 2; rr++) {
        const int row = bid * 2 + rr;
        float a[OUTC];
        #pragma unroll
        for (int o = 0; o < OUTC; o++) a[o] = 0.f;
        for (int k = tid; k < HID; k += NTH) {
            const float hv = g_h[(long)row * HID + k];
            const float* wr = Why + (long)k * OUTC;
            #pragma unroll
            for (int o = 0; o < OUTC; o++) a[o] += hv * wr[o];
        }
        #pragma unroll
        for (int o = 0; o < OUTC; o++)
            #pragma unroll
            for (int off = 16; off > 0; off >>= 1)
                a[o] += __shfl_down_sync(0xffffffffu, a[o], off);
        if (lane == 0) {
            #pragma unroll
            for (int o = 0; o < OUTC; o++) red[wid][o] = a[o];
        }
        __syncthreads();
        if (tid == 0) {
            float v[OUTC];
            float mx = -1e30f;
            #pragma unroll
            for (int o = 0; o < OUTC; o++) {
                float s8 = 0.f;
                #pragma unroll
                for (int w = 0; w < 8; w++) s8 += red[w][o];
                v[o] = s8 + bo[o];
                mx = fmaxf(mx, v[o]);
            }
            float s = 0.f;
            #pragma unroll
            for (int o = 0; o < OUTC; o++) { v[o] = expf(v[o] - mx); s += v[o]; }
            const float inv = 1.0f / s;
            #pragma unroll
            for (int o = 0; o < OUTC; o++) out[row * OUTC + o] = v[o] * inv;
        }
        __syncthreads();
    }
}

extern "C" void kernel_launch(void* const* d_in, const int* in_sizes, int n_in,
                              void* d_out, int out_size) {
    const float* x   = (const float*)d_in[0];
    const float* Whx = (const float*)d_in[1];
    const float* Whh = (const float*)d_in[2];
    const float* bh  = (const float*)d_in[3];
    const float* Why = (const float*)d_in[4];
    const float* bo  = (const float*)d_in[5];
    float* out = (float*)d_out;

    static int attr_done = 0;
    if (!attr_done) {
        cudaFuncSetAttribute(rnn_kernel,
                             cudaFuncAttributeMaxDynamicSharedMemorySize,
                             DSMB);
        attr_done = 1;
    }
    prep_kernel<<<1024, 256>>>(x, Whx, Whh);
    rnn_kernel<<<NCTA, NTH, DSMB>>>(bh, Why, bo, out);
}

// round 11
// speedup vs baseline: 1.6832x; 1.1370x over previous
#include <cuda_runtime.h>
#include <cuda_bf16.h>
#include <stdint.h>
#include <math.h>

#define BATCH 256
#define SEQ   256
#define IDIM  128
#define HID   1024
#define OUTC  10

#define NCTA  256
#define NTH   128
#define NSETS 4
#define SETROWS 64            // batch rows per set
#define SETC  64              // CTAs per set
#define GK16W 1024            // words per k16 A tile (64 rows * 16)
#define BGKW  2048            // words per k16 B tile (128 rows * 16)
#define NBGK  9               // B k16-groups per CTA (1 x + 8 h)
#define SBW   (NBGK * BGKW)   // 18432 words (72KB)
#define SAW   (2 * 2 * GK16W) // A: 2 bufs x 2 subs (16KB)
#define DSMW  (SBW + SAW)
#define DSMB  (DSMW * 4)      // 90112 bytes

// -------- device globals --------
__device__ uint32_t g_xs[(long)BATCH * SEQ * 8 * 16];    // packed x slots
__device__ uint32_t g_bs[8L * 8 * NBGK * 128 * 16];      // packed W slabs
__device__ uint32_t g_hs[2][BATCH * 64 * 16];            // packed h, parity-buffered
__device__ float    g_h[BATCH * HID];                    // plain h (final step)
__device__ float4   g_part[2][NCTA * 4 * 16 * 32];       // partials, parity-buffered
__device__ unsigned int g_pdone[NSETS][8 * 32];          // per-(set,tile) partial ctrs
__device__ unsigned int g_hdone[NSETS][8 * 32];          // per-(set,tile) h ctrs

// -------- helpers --------
static __device__ __forceinline__ uint32_t pk2(float a, float b) {
    __nv_bfloat162 t = __floats2bfloat162_rn(a, b);
    return *reinterpret_cast<uint32_t*>(&t);
}
static __device__ __forceinline__ float bf16rt(float v) {
    return __bfloat162float(__float2bfloat16_rn(v));
}
static __device__ __forceinline__ void mma16(float* c,
        uint32_t a0, uint32_t a1, uint32_t a2, uint32_t a3,
        uint32_t b0, uint32_t b1) {
    asm volatile(
        "mma.sync.aligned.m16n8k16.row.col.f32.bf16.bf16.f32 "
        "{%0,%1,%2,%3},{%4,%5,%6,%7},{%8,%9},{%0,%1,%2,%3};"
        : "+f"(c[0]), "+f"(c[1]), "+f"(c[2]), "+f"(c[3])
        : "r"(a0), "r"(a1), "r"(a2), "r"(a3), "r"(b0), "r"(b1));
}
static __device__ __forceinline__ float my_tanh(float v) {
    float e = __expf(2.0f * v);
    return 1.0f - 2.0f / (e + 1.0f);
}
static __device__ __forceinline__ void pack16(const float* v, uint4* dst) {
    #pragma unroll
    for (int t = 0; t < 4; t++) {
        const float a0 = v[2*t],   a1 = v[2*t+1];
        const float a8 = v[2*t+8], a9 = v[2*t+9];
        uint4 s;
        s.x = pk2(a0, a1);
        s.y = pk2(a8, a9);
        s.z = pk2(a0 - bf16rt(a0), a1 - bf16rt(a1));
        s.w = pk2(a8 - bf16rt(a8), a9 - bf16rt(a9));
        dst[t] = s;
    }
}

// -------- prep --------
__global__ void prep_kernel(const float* __restrict__ x,
                            const float* __restrict__ Whx,
                            const float* __restrict__ Whh) {
    const long tid = (long)blockIdx.x * blockDim.x + threadIdx.x;
    const long nt  = (long)gridDim.x * blockDim.x;
    for (long i = tid; i < (long)BATCH * SEQ * 8; i += nt) {
        const long bt = i >> 3;
        const int  g  = (int)(i & 7);
        const float* src = x + bt * IDIM + g * 16;
        float v[16];
        #pragma unroll
        for (int j = 0; j < 16; j++) v[j] = src[j];
        pack16(v, (uint4*)(g_xs + i * 16));
    }
    for (long i = tid; i < 8L * 8 * NBGK * 128; i += nt) {
        const int col = (int)(i & 127);
        long tmp = i >> 7;
        const int c  = (int)(tmp % NBGK); tmp /= NBGK;
        const int ks = (int)(tmp & 7);
        const int tn = (int)(tmp >> 3);
        const int n  = tn * 128 + col;
        const int kbase = (c == 0) ? (HID + ks * 16) : (ks * 128 + (c - 1) * 16);
        float v[16];
        #pragma unroll
        for (int j = 0; j < 16; j++) {
            const int k = kbase + j;
            v[j] = (k < HID) ? Whh[(long)k * HID + n] : Whx[(long)(k - HID) * HID + n];
        }
        pack16(v, (uint4*)(g_bs + i * 16));
    }
    for (long i = tid; i < (long)BATCH * 64 * 16; i += nt) g_hs[0][i] = 0u;
    for (long i = tid; i < (long)BATCH * HID; i += nt)     g_h[i]  = 0.f;
    if (tid < NSETS * 8 * 32) {
        g_pdone[tid / (8 * 32)][tid % (8 * 32)] = 0u;
        g_hdone[tid / (8 * 32)][tid % (8 * 32)] = 0u;
    }
}

// -------- main persistent kernel: 256 CTAs x 128 thr, 2 CTAs/SM --------
__global__ void __launch_bounds__(NTH, 2)
rnn_kernel(const float* __restrict__ bh,
           const float* __restrict__ Why,
           const float* __restrict__ bo,
           float* __restrict__ out) {
    extern __shared__ uint32_t dsm[];
    uint32_t* sB = dsm;            // resident B slab: [gk][128 rows][16]
    uint32_t* sA = dsm + SBW;      // [buf][sub][64 rows][16]
    __shared__ float red[4][OUTC];

    const int tid  = threadIdx.x;
    const int bid  = blockIdx.x;
    const int wid  = tid >> 5;     // 0..3  (= warp N position)
    const int lane = tid & 31;

    const int set   = bid >> 6;          // 0..3 (batch quarter)
    const int sbid  = bid & 63;
    const int tileN = sbid >> 3;
    const int ks    = sbid & 7;
    const int m0    = set * SETROWS;
    const int n0    = tileN * 128;

    const int grp = lane >> 2;
    const int tig = lane & 3;

    const int rrow = tid >> 1;     // 0..63
    const int half = tid & 1;

    const int aoff = grp * 16 + tig * 4;                 // A: 64-row tile
    const int boff = (wid * 32 + grp) * 16 + tig * 4;    // B: 128-row tile

    unsigned int* my_pctr = &g_pdone[set][tileN * 32];
    unsigned int* my_hctr = &g_hdone[set][tileN * 32];
    volatile unsigned int* dep_hctr = &g_hdone[set][ks * 32];

    // ---- preload resident B slab ----
    {
        const uint4* bsrc = (const uint4*)g_bs + (long)(tileN * 8 + ks) * (NBGK * 512);
        uint4* dst = (uint4*)sB;
        for (int i = tid; i < NBGK * 512; i += NTH) dst[i] = bsrc[i];
    }
    __syncthreads();

    // reduce-phase constants: fragment f = ks*8 + wid*2 + it
    int   r_m[2], r_n[2], r_hoff[2];
    long  r_pbase[2];
    float r_b0[2], r_b1[2];
    #pragma unroll
    for (int it = 0; it < 2; it++) {
        const int f  = ks * 8 + wid * 2 + it;
        const int w  = f >> 4;               // source warp (N pos)
        const int qq = f & 15;
        const int mt = qq >> 2, nt = qq & 3;
        r_m[it] = m0 + mt * 16 + (lane >> 2);
        r_n[it] = n0 + w * 32 + nt * 8 + (lane & 3) * 2;
        r_pbase[it] = ((long)(set * 64 + tileN * 8) * 4 + w) * 16 + qq;  // +k2*64
        r_b0[it] = bh[r_n[it]];
        r_b1[it] = bh[r_n[it] + 1];
        const int j = r_n[it] & 15;
        r_hoff[it] = (r_m[it] * 64 + (r_n[it] >> 4)) * 16 +
                     ((j < 8) ? (j >> 1) * 4 : ((j - 8) >> 1) * 4 + 1);
    }

    float acc[4][4][4];
    uint4 u[4];
    const uint32_t* hbase_cur;

    auto compute16 = [&](int gk, const uint32_t* ab) {
        uint4 ra[4][2];
        const uint32_t* ap = ab + aoff;
        #pragma unroll
        for (int mt = 0; mt < 4; mt++) {
            ra[mt][0] = *(const uint4*)(ap + mt * 256);
            ra[mt][1] = *(const uint4*)(ap + mt * 256 + 128);
        }
        const uint32_t* bb = sB + gk * BGKW + boff;
        #pragma unroll
        for (int nt = 0; nt < 4; nt++) {
            const uint4 bv = *(const uint4*)(bb + nt * 128);
            #pragma unroll
            for (int mt = 0; mt < 4; mt++) {
                mma16(acc[mt][nt], ra[mt][0].x, ra[mt][1].x, ra[mt][0].y, ra[mt][1].y, bv.x, bv.y);
                mma16(acc[mt][nt], ra[mt][0].x, ra[mt][1].x, ra[mt][0].y, ra[mt][1].y, bv.z, bv.w);
                mma16(acc[mt][nt], ra[mt][0].z, ra[mt][1].z, ra[mt][0].w, ra[mt][1].w, bv.x, bv.y);
            }
        }
    };
    auto ldg_h = [&](int i) {
        const uint32_t* src = hbase_cur +
            ((long)(m0 + rrow) * 64 + ks * 8 + 2 * i + half) * 16;
        #pragma unroll
        for (int w = 0; w < 4; w++) u[w] = ((const uint4*)src)[w];
    };
    auto sts_h = [&](int buf) {
        uint4* d = (uint4*)(sA + buf * (2 * GK16W) + half * GK16W + rrow * 16);
        #pragma unroll
        for (int w = 0; w < 4; w++) d[w] = u[w];
    };

    for (int t = 0; t < SEQ; t++) {
        #pragma unroll
        for (int mt = 0; mt < 4; mt++)
            #pragma unroll
            for (int nt = 0; nt < 4; nt++)
                #pragma unroll
                for (int c = 0; c < 4; c++)
                    acc[mt][nt][c] = 0.f;

        // ---- x chunk (k16, h-independent) ----
        {
            const uint32_t* src = g_xs +
                (((long)(m0 + rrow) * SEQ + t) * 8 + ks) * 16 + half * 8;
            uint4 a0 = ((const uint4*)src)[0];
            uint4 a1 = ((const uint4*)src)[1];
            uint4* d = (uint4*)(sA + rrow * 16 + half * 8);   // buf0 sub0
            d[0] = a0;
            d[1] = a1;
        }
        __syncthreads();
        compute16(0, sA);

        // ---- wait: tile `ks` of my set finished reduce of step t-1 ----
        if (tid == 0) {
            const unsigned target = 8u * (unsigned)t;
            while (*dep_hctr < target) { }
        }
        __syncthreads();
        __threadfence();

        hbase_cur = g_hs[t & 1];

        // ---- 4 h chunks (k32 each), double-buffered ----
        ldg_h(0);
        sts_h(1);
        __syncthreads();
        #pragma unroll 1
        for (int i = 0; i < 4; i++) {
            if (i < 3) ldg_h(i + 1);
            const uint32_t* ab = sA + (((i + 1) & 1) * 2) * GK16W;
            compute16(1 + 2 * i,     ab);
            compute16(1 + 2 * i + 1, ab + GK16W);
            if (i < 3) {
                sts_h(i & 1);
                __syncthreads();
            }
        }

        // ---- store partials (parity t) + signal ----
        {
            float4* pp = g_part[t & 1] + ((long)(bid * 4 + wid) * 16) * 32 + lane;
            #pragma unroll
            for (int mt = 0; mt < 4; mt++)
                #pragma unroll
                for (int nt = 0; nt < 4; nt++) {
                    const int q = mt * 4 + nt;
                    pp[q * 32] = make_float4(acc[mt][nt][0], acc[mt][nt][1],
                                             acc[mt][nt][2], acc[mt][nt][3]);
                }
        }
        __syncthreads();
        if (tid == 0) {
            __threadfence();
            atomicAdd(my_pctr, 1u);
        }

        // ---- wait: my tile's 8 partials stored ----
        if (tid == 0) {
            const unsigned target = 8u * (unsigned)(t + 1);
            volatile unsigned int* p = my_pctr;
            while (*p < target) { }
        }
        __syncthreads();
        __threadfence();

        // ---- reduce: sum 8 K-splits, bias+tanh, write packed h (parity t+1) ----
        {
            const float4* pbuf = g_part[t & 1];
            uint32_t* hdst = g_hs[(t + 1) & 1];
            #pragma unroll
            for (int it = 0; it < 2; it++) {
                float s0 = 0.f, s1 = 0.f, s2 = 0.f, s3 = 0.f;
                #pragma unroll
                for (int k2 = 0; k2 < 8; k2++) {
                    float4 v = pbuf[(r_pbase[it] + (long)k2 * 64) * 32 + lane];
                    s0 += v.x; s1 += v.y; s2 += v.z; s3 += v.w;
                }
                const float t0 = my_tanh(s0 + r_b0[it]);
                const float t1 = my_tanh(s1 + r_b1[it]);
                const float t2 = my_tanh(s2 + r_b0[it]);
                const float t3 = my_tanh(s3 + r_b1[it]);
                const float f0 = bf16rt(t0), f1 = bf16rt(t1);
                const float f2 = bf16rt(t2), f3 = bf16rt(t3);
                hdst[r_hoff[it]]            = pk2(t0, t1);
                hdst[r_hoff[it] + 2]        = pk2(t0 - f0, t1 - f1);
                hdst[r_hoff[it] + 8192]     = pk2(t2, t3);   // +8 rows = 8*64*16
                hdst[r_hoff[it] + 8192 + 2] = pk2(t2 - f2, t3 - f3);
                if (t == SEQ - 1) {
                    g_h[(long)r_m[it] * HID + r_n[it]]           = t0;
                    g_h[(long)r_m[it] * HID + r_n[it] + 1]       = t1;
                    g_h[(long)(r_m[it] + 8) * HID + r_n[it]]     = t2;
                    g_h[(long)(r_m[it] + 8) * HID + r_n[it] + 1] = t3;
                }
            }
        }
        __syncthreads();
        if (tid == 0) {
            __threadfence();
            atomicAdd(my_hctr, 1u);
        }
    }

    // ---- wait for all tiles of my set ----
    if (tid < 8) {
        volatile unsigned int* p = &g_hdone[set][tid * 32];
        const unsigned target = 8u * (unsigned)SEQ;
        while (*p < target) { }
    }
    __syncthreads();
    __threadfence();

    // ---- classifier + softmax: 1 row per CTA (row bid is in my set) ----
    {
        const int row = bid;
        float a[OUTC];
        #pragma unroll
        for (int o = 0; o < OUTC; o++) a[o] = 0.f;
        for (int k = tid; k < HID; k += NTH) {
            const float hv = g_h[(long)row * HID + k];
            const float* wr = Why + (long)k * OUTC;
            #pragma unroll
            for (int o = 0; o < OUTC; o++) a[o] += hv * wr[o];
        }
        #pragma unroll
        for (int o = 0; o < OUTC; o++)
            #pragma unroll
            for (int off = 16; off > 0; off >>= 1)
                a[o] += __shfl_down_sync(0xffffffffu, a[o], off);
        if (lane == 0) {
            #pragma unroll
            for (int o = 0; o < OUTC; o++) red[wid][o] = a[o];
        }
        __syncthreads();
        if (tid == 0) {
            float v[OUTC];
            float mx = -1e30f;
            #pragma unroll
            for (int o = 0; o < OUTC; o++) {
                v[o] = red[0][o] + red[1][o] + red[2][o] + red[3][o] + bo[o];
                mx = fmaxf(mx, v[o]);
            }
            float s = 0.f;
            #pragma unroll
            for (int o = 0; o < OUTC; o++) { v[o] = expf(v[o] - mx); s += v[o]; }
            const float inv = 1.0f / s;
            #pragma unroll
            for (int o = 0; o < OUTC; o++) out[row * OUTC + o] = v[o] * inv;
        }
    }
}

extern "C" void kernel_launch(void* const* d_in, const int* in_sizes, int n_in,
                              void* d_out, int out_size) {
    const float* x   = (const float*)d_in[0];
    const float* Whx = (const float*)d_in[1];
    const float* Whh = (const float*)d_in[2];
    const float* bh  = (const float*)d_in[3];
    const float* Why = (const float*)d_in[4];
    const float* bo  = (const float*)d_in[5];
    float* out = (float*)d_out;

    static int attr_done = 0;
    if (!attr_done) {
        cudaFuncSetAttribute(rnn_kernel,
                             cudaFuncAttributeMaxDynamicSharedMemorySize,
                             DSMB);
        attr_done = 1;
    }
    prep_kernel<<<1024, 256>>>(x, Whx, Whh);
    rnn_kernel<<<NCTA, NTH, DSMB>>>(bh, Why, bo, out);
}

// round 12
// speedup vs baseline: 2.0554x; 1.2211x over previous
#include <cuda_runtime.h>
#include <cuda_bf16.h>
#include <stdint.h>
#include <math.h>

#define BATCH 256
#define SEQ   256
#define IDIM  128
#define HID   1024
#define OUTC  10

#define NCTA  512
#define NTH   128
#define NSETS 8
#define SETROWS 32

// -------- device globals --------
__device__ uint32_t g_xs[(long)BATCH * SEQ * 8 * 16];    // packed x slots
__device__ uint32_t g_bs[8L * 8 * 9 * 128 * 16];         // packed W slabs (4.7MB)
__device__ uint32_t g_hs[2][BATCH * 64 * 16];            // packed h, parity-buffered
__device__ float    g_h[BATCH * HID];                    // plain h (final step)
__device__ float4   g_part[2][(long)NCTA * 4 * 8 * 32];  // partials, parity-buffered
__device__ unsigned int g_pdone[NSETS][8 * 32];
__device__ unsigned int g_hdone[NSETS][8 * 32];

// -------- helpers --------
static __device__ __forceinline__ uint32_t pk2(float a, float b) {
    __nv_bfloat162 t = __floats2bfloat162_rn(a, b);
    return *reinterpret_cast<uint32_t*>(&t);
}
static __device__ __forceinline__ float bf16rt(float v) {
    return __bfloat162float(__float2bfloat16_rn(v));
}
static __device__ __forceinline__ void mma16(float* c,
        uint32_t a0, uint32_t a1, uint32_t a2, uint32_t a3,
        uint32_t b0, uint32_t b1) {
    asm volatile(
        "mma.sync.aligned.m16n8k16.row.col.f32.bf16.bf16.f32 "
        "{%0,%1,%2,%3},{%4,%5,%6,%7},{%8,%9},{%0,%1,%2,%3};"
        : "+f"(c[0]), "+f"(c[1]), "+f"(c[2]), "+f"(c[3])
        : "r"(a0), "r"(a1), "r"(a2), "r"(a3), "r"(b0), "r"(b1));
}
static __device__ __forceinline__ float my_tanh(float v) {
    float e = __expf(2.0f * v);
    return 1.0f - 2.0f / (e + 1.0f);
}
static __device__ __forceinline__ void pack16(const float* v, uint4* dst) {
    #pragma unroll
    for (int t = 0; t < 4; t++) {
        const float a0 = v[2*t],   a1 = v[2*t+1];
        const float a8 = v[2*t+8], a9 = v[2*t+9];
        uint4 s;
        s.x = pk2(a0, a1);
        s.y = pk2(a8, a9);
        s.z = pk2(a0 - bf16rt(a0), a1 - bf16rt(a1));
        s.w = pk2(a8 - bf16rt(a8), a9 - bf16rt(a9));
        dst[t] = s;
    }
}

// -------- prep --------
__global__ void prep_kernel(const float* __restrict__ x,
                            const float* __restrict__ Whx,
                            const float* __restrict__ Whh) {
    const long tid = (long)blockIdx.x * blockDim.x + threadIdx.x;
    const long nt  = (long)gridDim.x * blockDim.x;
    for (long i = tid; i < (long)BATCH * SEQ * 8; i += nt) {
        const long bt = i >> 3;
        const int  g  = (int)(i & 7);
        const float* src = x + bt * IDIM + g * 16;
        float v[16];
        #pragma unroll
        for (int j = 0; j < 16; j++) v[j] = src[j];
        pack16(v, (uint4*)(g_xs + i * 16));
    }
    for (long i = tid; i < 8L * 8 * 9 * 128; i += nt) {
        const int col = (int)(i & 127);
        long tmp = i >> 7;
        const int c  = (int)(tmp % 9); tmp /= 9;
        const int ks = (int)(tmp & 7);
        const int tn = (int)(tmp >> 3);
        const int n  = tn * 128 + col;
        const int kbase = (c == 0) ? (HID + ks * 16) : (ks * 128 + (c - 1) * 16);
        float v[16];
        #pragma unroll
        for (int j = 0; j < 16; j++) {
            const int k = kbase + j;
            v[j] = (k < HID) ? Whh[(long)k * HID + n] : Whx[(long)(k - HID) * HID + n];
        }
        pack16(v, (uint4*)(g_bs + i * 16));
    }
    for (long i = tid; i < (long)BATCH * 64 * 16; i += nt) g_hs[0][i] = 0u;
    for (long i = tid; i < (long)BATCH * HID; i += nt)     g_h[i]  = 0.f;
    if (tid < NSETS * 8 * 32) {
        g_pdone[tid / (8 * 32)][tid % (8 * 32)] = 0u;
        g_hdone[tid / (8 * 32)][tid % (8 * 32)] = 0u;
    }
}

// -------- main persistent kernel: 512 CTAs x 128 thr, 4 CTAs/SM --------
__global__ void __launch_bounds__(NTH, 4)
rnn_kernel(const float* __restrict__ bh,
           const float* __restrict__ Why,
           const float* __restrict__ bo,
           float* __restrict__ out) {
    __shared__ uint32_t sA[2 * 2 * 512];   // [buf][sub][32 rows *16 words] = 8KB
    __shared__ float red[4][OUTC];

    const int tid  = threadIdx.x;
    const int bid  = blockIdx.x;
    const int wid  = tid >> 5;     // warp = N position 0..3
    const int lane = tid & 31;

    const int set   = bid >> 6;          // 0..7 (32 batch rows each)
    const int sbid  = bid & 63;
    const int tileN = sbid >> 3;
    const int ks    = sbid & 7;
    const int m0    = set * SETROWS;
    const int n0    = tileN * 128;

    const int grp = lane >> 2;
    const int tig = lane & 3;

    const int arow = tid >> 2;     // staging row 0..31
    const int aq   = tid & 3;      // staging uint4 slot

    unsigned int* my_pctr = &g_pdone[set][tileN * 32];
    unsigned int* my_hctr = &g_hdone[set][tileN * 32];
    volatile unsigned int* dep_hctr = &g_hdone[set][ks * 32];

    // B gmem base (uint4 units): [(tileN*8+ks)][gk][row][4 uint4]
    const uint4* bslab = (const uint4*)g_bs + (long)(tileN * 8 + ks) * (9 * 512);
    const int bfrag = (wid * 32 + grp) * 4 + tig;   // + nt*8*4 per nt, + gk*512

    // reduce constants: 1 fragment per warp, f = ks*4 + wid
    const int f   = ks * 4 + wid;
    const int fmt = f >> 4;
    const int fw  = (f >> 2) & 3;
    const int fnt = f & 3;
    const int fq  = fmt * 4 + fnt;
    const int r_m = m0 + fmt * 16 + (lane >> 2);
    const int r_n = n0 + fw * 32 + fnt * 8 + (lane & 3) * 2;
    const long r_pbase = (((long)(set * 64 + tileN * 8) * 4 + fw) * 8 + fq) * 32 + lane;
    const float r_b0 = bh[r_n];
    const float r_b1 = bh[r_n + 1];
    const int jj = r_n & 15;
    const int r_hoff = (r_m * 64 + (r_n >> 4)) * 16 +
                       ((jj < 8) ? (jj >> 1) * 4 : ((jj - 8) >> 1) * 4 + 1);

    float acc[2][4][4];
    uint4 u0, u1;
    uint4 bvP[4], bvQ[4];
    const uint32_t* hbase_cur;

    auto ldgB = [&](int gk, uint4* bv) {
        const uint4* src = bslab + gk * 512 + bfrag;
        #pragma unroll
        for (int nt = 0; nt < 4; nt++) bv[nt] = src[nt * 32];
    };
    auto compute16 = [&](const uint4* bv, const uint32_t* ab) {
        const uint32_t* ap = ab + grp * 16 + tig * 4;
        uint4 ra[2][2];
        #pragma unroll
        for (int mt = 0; mt < 2; mt++) {
            ra[mt][0] = *(const uint4*)(ap + mt * 256);
            ra[mt][1] = *(const uint4*)(ap + mt * 256 + 128);
        }
        #pragma unroll
        for (int nt = 0; nt < 4; nt++) {
            #pragma unroll
            for (int mt = 0; mt < 2; mt++) {
                mma16(acc[mt][nt], ra[mt][0].x, ra[mt][1].x, ra[mt][0].y, ra[mt][1].y,
                      bv[nt].x, bv[nt].y);
                mma16(acc[mt][nt], ra[mt][0].x, ra[mt][1].x, ra[mt][0].y, ra[mt][1].y,
                      bv[nt].z, bv[nt].w);
                mma16(acc[mt][nt], ra[mt][0].z, ra[mt][1].z, ra[mt][0].w, ra[mt][1].w,
                      bv[nt].x, bv[nt].y);
            }
        }
    };
    auto ldg_h = [&](int i) {
        const uint4* src = (const uint4*)hbase_cur +
            ((long)(m0 + arow) * 64 + ks * 8 + 2 * i) * 4 + aq;
        u0 = src[0];
        u1 = src[4];        // sub 1 = next slot group (+16 words = +4 uint4)
    };
    auto sts_h = [&](int buf) {
        uint4* d = (uint4*)sA + buf * 256 + arow * 4 + aq;
        d[0]   = u0;
        d[128] = u1;        // sub 1 at +512 words = +128 uint4
    };

    for (int t = 0; t < SEQ; t++) {
        #pragma unroll
        for (int mt = 0; mt < 2; mt++)
            #pragma unroll
            for (int nt = 0; nt < 4; nt++)
                #pragma unroll
                for (int c = 0; c < 4; c++)
                    acc[mt][nt][c] = 0.f;

        // ---- x chunk (k16, h-independent) ----
        ldgB(0, bvP);
        {
            const uint4* src = (const uint4*)g_xs +
                (((long)(m0 + arow) * SEQ + t) * 8 + ks) * 4 + aq;
            uint4 xv = src[0];
            ((uint4*)sA)[arow * 4 + aq] = xv;     // buf0 sub0
        }
        __syncthreads();
        compute16(bvP, sA);
        ldgB(1, bvP);       // prefetch first h group (B is h-independent)

        // ---- wait: producer tile `ks` finished reduce of step t-1 ----
        if (tid == 0) {
            const unsigned target = 8u * (unsigned)t;
            while (*dep_hctr < target) { }
        }
        __syncthreads();
        __threadfence();

        hbase_cur = g_hs[t & 1];

        // ---- 4 h chunks (k32), A double-buffered, B register-pipelined ----
        ldg_h(0);
        sts_h(1);
        __syncthreads();
        #pragma unroll 1
        for (int i = 0; i < 4; i++) {
            if (i < 3) ldg_h(i + 1);
            ldgB(2 + 2 * i, bvQ);
            const uint32_t* ab = sA + (((i + 1) & 1) * 1024);
            compute16(bvP, ab);                    // group 1+2i
            if (i < 3) ldgB(3 + 2 * i, bvP);       // next chunk's first half
            compute16(bvQ, ab + 512);              // group 2+2i
            if (i < 3) {
                sts_h(i & 1);
                __syncthreads();
            }
        }

        // ---- store partials (parity t) + signal ----
        {
            float4* pp = &g_part[t & 1][((long)(bid * 4 + wid) * 8) * 32 + lane];
            #pragma unroll
            for (int mt = 0; mt < 2; mt++)
                #pragma unroll
                for (int nt = 0; nt < 4; nt++) {
                    const int q = mt * 4 + nt;
                    pp[q * 32] = make_float4(acc[mt][nt][0], acc[mt][nt][1],
                                             acc[mt][nt][2], acc[mt][nt][3]);
                }
        }
        __syncthreads();
        if (tid == 0) {
            __threadfence();
            atomicAdd(my_pctr, 1u);
        }

        // ---- wait: my tile's 8 partials stored ----
        if (tid == 0) {
            const unsigned target = 8u * (unsigned)(t + 1);
            volatile unsigned int* p = my_pctr;
            while (*p < target) { }
        }
        __syncthreads();
        __threadfence();

        // ---- reduce: 1 fragment per warp ----
        {
            const float4* pbuf = g_part[t & 1];
            uint32_t* hdst = g_hs[(t + 1) & 1];
            float s0 = 0.f, s1 = 0.f, s2 = 0.f, s3 = 0.f;
            #pragma unroll
            for (int k2 = 0; k2 < 8; k2++) {
                float4 v = pbuf[r_pbase + (long)k2 * (4 * 8 * 32)];
                s0 += v.x; s1 += v.y; s2 += v.z; s3 += v.w;
            }
            const float t0 = my_tanh(s0 + r_b0);
            const float t1 = my_tanh(s1 + r_b1);
            const float t2 = my_tanh(s2 + r_b0);
            const float t3 = my_tanh(s3 + r_b1);
            const float f0 = bf16rt(t0), f1 = bf16rt(t1);
            const float f2 = bf16rt(t2), f3 = bf16rt(t3);
            hdst[r_hoff]            = pk2(t0, t1);
            hdst[r_hoff + 2]        = pk2(t0 - f0, t1 - f1);
            hdst[r_hoff + 8192]     = pk2(t2, t3);      // +8 rows = 8*64*16 words
            hdst[r_hoff + 8192 + 2] = pk2(t2 - f2, t3 - f3);
            if (t == SEQ - 1) {
                g_h[(long)r_m * HID + r_n]           = t0;
                g_h[(long)r_m * HID + r_n + 1]       = t1;
                g_h[(long)(r_m + 8) * HID + r_n]     = t2;
                g_h[(long)(r_m + 8) * HID + r_n + 1] = t3;
            }
        }
        __syncthreads();
        if (tid == 0) {
            __threadfence();
            atomicAdd(my_hctr, 1u);
        }
    }

    // ---- classifier + softmax: CTAs 0..255 handle one row each ----
    if (bid < BATCH) {
        const int row  = bid;
        const int setr = row >> 5;       // the set that owns this row
        if (tid < 8) {
            volatile unsigned int* p = &g_hdone[setr][tid * 32];
            const unsigned target = 8u * (unsigned)SEQ;
            while (*p < target) { }
        }
        __syncthreads();
        __threadfence();

        float a[OUTC];
        #pragma unroll
        for (int o = 0; o < OUTC; o++) a[o] = 0.f;
        for (int k = tid; k < HID; k += NTH) {
            const float hv = g_h[(long)row * HID + k];
            const float* wr = Why + (long)k * OUTC;
            #pragma unroll
            for (int o = 0; o < OUTC; o++) a[o] += hv * wr[o];
        }
        #pragma unroll
        for (int o = 0; o < OUTC; o++)
            #pragma unroll
            for (int off = 16; off > 0; off >>= 1)
                a[o] += __shfl_down_sync(0xffffffffu, a[o], off);
        if (lane == 0) {
            #pragma unroll
            for (int o = 0; o < OUTC; o++) red[wid][o] = a[o];
        }
        __syncthreads();
        if (tid == 0) {
            float v[OUTC];
            float mx = -1e30f;
            #pragma unroll
            for (int o = 0; o < OUTC; o++) {
                v[o] = red[0][o] + red[1][o] + red[2][o] + red[3][o] + bo[o];
                mx = fmaxf(mx, v[o]);
            }
            float s = 0.f;
            #pragma unroll
            for (int o = 0; o < OUTC; o++) { v[o] = expf(v[o] - mx); s += v[o]; }
            const float inv = 1.0f / s;
            #pragma unroll
            for (int o = 0; o < OUTC; o++) out[row * OUTC + o] = v[o] * inv;
        }
    }
}

extern "C" void kernel_launch(void* const* d_in, const int* in_sizes, int n_in,
                              void* d_out, int out_size) {
    const float* x   = (const float*)d_in[0];
    const float* Whx = (const float*)d_in[1];
    const float* Whh = (const float*)d_in[2];
    const float* bh  = (const float*)d_in[3];
    const float* Why = (const float*)d_in[4];
    const float* bo  = (const float*)d_in[5];
    float* out = (float*)d_out;

    prep_kernel<<<1024, 256>>>(x, Whx, Whh);
    rnn_kernel<<<NCTA, NTH>>>(bh, Why, bo, out);
}

// round 13
// speedup vs baseline: 2.2545x; 1.0969x over previous
#include <cuda_runtime.h>
#include <cuda_bf16.h>
#include <stdint.h>
#include <math.h>

#define BATCH 256
#define SEQ   256
#define IDIM  128
#define HID   1024
#define OUTC  10

#define NCTA  512
#define NTH   128
#define NSETS 8
#define SETROWS 32

// -------- device globals --------
__device__ uint32_t g_xs[(long)BATCH * SEQ * 8 * 16];    // packed x slots
__device__ uint32_t g_bs[8L * 8 * 9 * 128 * 16];         // packed W slabs (4.7MB)
__device__ uint32_t g_hs[2][BATCH * 64 * 16];            // packed h, parity-buffered
__device__ float    g_h[BATCH * HID];                    // plain h (final step)
__device__ float4   g_part[2][(long)NCTA * 4 * 8 * 32];  // partials, parity-buffered
__device__ unsigned int g_pdone[NSETS][8 * 32];
__device__ unsigned int g_hdone[NSETS][8 * 32];

// -------- helpers --------
static __device__ __forceinline__ uint32_t pk2(float a, float b) {
    __nv_bfloat162 t = __floats2bfloat162_rn(a, b);
    return *reinterpret_cast<uint32_t*>(&t);
}
static __device__ __forceinline__ float bf16rt(float v) {
    return __bfloat162float(__float2bfloat16_rn(v));
}
static __device__ __forceinline__ void mma16(float* c,
        uint32_t a0, uint32_t a1, uint32_t a2, uint32_t a3,
        uint32_t b0, uint32_t b1) {
    asm volatile(
        "mma.sync.aligned.m16n8k16.row.col.f32.bf16.bf16.f32 "
        "{%0,%1,%2,%3},{%4,%5,%6,%7},{%8,%9},{%0,%1,%2,%3};"
        : "+f"(c[0]), "+f"(c[1]), "+f"(c[2]), "+f"(c[3])
        : "r"(a0), "r"(a1), "r"(a2), "r"(a3), "r"(b0), "r"(b1));
}
static __device__ __forceinline__ float my_tanh(float v) {
    float e = __expf(2.0f * v);
    return 1.0f - 2.0f / (e + 1.0f);
}
// release-signal: prior writes ordered before the increment (gpu scope)
static __device__ __forceinline__ void sig_release(unsigned int* p) {
    asm volatile("red.release.gpu.global.add.u32 [%0], 1;" :: "l"(p) : "memory");
}
// acquire-poll read
static __device__ __forceinline__ unsigned ld_acq(const unsigned int* p) {
    unsigned v;
    asm volatile("ld.acquire.gpu.global.u32 %0, [%1];" : "=r"(v) : "l"(p) : "memory");
    return v;
}
static __device__ __forceinline__ void pack16(const float* v, uint4* dst) {
    #pragma unroll
    for (int t = 0; t < 4; t++) {
        const float a0 = v[2*t],   a1 = v[2*t+1];
        const float a8 = v[2*t+8], a9 = v[2*t+9];
        uint4 s;
        s.x = pk2(a0, a1);
        s.y = pk2(a8, a9);
        s.z = pk2(a0 - bf16rt(a0), a1 - bf16rt(a1));
        s.w = pk2(a8 - bf16rt(a8), a9 - bf16rt(a9));
        dst[t] = s;
    }
}

// -------- prep --------
__global__ void prep_kernel(const float* __restrict__ x,
                            const float* __restrict__ Whx,
                            const float* __restrict__ Whh) {
    const long tid = (long)blockIdx.x * blockDim.x + threadIdx.x;
    const long nt  = (long)gridDim.x * blockDim.x;
    for (long i = tid; i < (long)BATCH * SEQ * 8; i += nt) {
        const long bt = i >> 3;
        const int  g  = (int)(i & 7);
        const float* src = x + bt * IDIM + g * 16;
        float v[16];
        #pragma unroll
        for (int j = 0; j < 16; j++) v[j] = src[j];
        pack16(v, (uint4*)(g_xs + i * 16));
    }
    for (long i = tid; i < 8L * 8 * 9 * 128; i += nt) {
        const int col = (int)(i & 127);
        long tmp = i >> 7;
        const int c  = (int)(tmp % 9); tmp /= 9;
        const int ks = (int)(tmp & 7);
        const int tn = (int)(tmp >> 3);
        const int n  = tn * 128 + col;
        const int kbase = (c == 0) ? (HID + ks * 16) : (ks * 128 + (c - 1) * 16);
        float v[16];
        #pragma unroll
        for (int j = 0; j < 16; j++) {
            const int k = kbase + j;
            v[j] = (k < HID) ? Whh[(long)k * HID + n] : Whx[(long)(k - HID) * HID + n];
        }
        pack16(v, (uint4*)(g_bs + i * 16));
    }
    for (long i = tid; i < (long)BATCH * 64 * 16; i += nt) g_hs[0][i] = 0u;
    for (long i = tid; i < (long)BATCH * HID; i += nt)     g_h[i]  = 0.f;
    if (tid < NSETS * 8 * 32) {
        g_pdone[tid / (8 * 32)][tid % (8 * 32)] = 0u;
        g_hdone[tid / (8 * 32)][tid % (8 * 32)] = 0u;
    }
}

// -------- main persistent kernel: 512 CTAs x 128 thr, 4 CTAs/SM --------
__global__ void __launch_bounds__(NTH, 4)
rnn_kernel(const float* __restrict__ bh,
           const float* __restrict__ Why,
           const float* __restrict__ bo,
           float* __restrict__ out) {
    __shared__ uint32_t sA[2 * 2 * 512];   // [buf][sub][32 rows *16 words] = 8KB
    __shared__ float red[4][OUTC];

    const int tid  = threadIdx.x;
    const int bid  = blockIdx.x;
    const int wid  = tid >> 5;     // warp = N position 0..3
    const int lane = tid & 31;

    const int set   = bid >> 6;          // 0..7 (32 batch rows each)
    const int sbid  = bid & 63;
    const int tileN = sbid >> 3;
    const int ks    = sbid & 7;
    const int m0    = set * SETROWS;
    const int n0    = tileN * 128;

    const int grp = lane >> 2;
    const int tig = lane & 3;

    const int arow = tid >> 2;     // staging row 0..31
    const int aq   = tid & 3;      // staging uint4 slot

    unsigned int* my_pctr = &g_pdone[set][tileN * 32];
    unsigned int* my_hctr = &g_hdone[set][tileN * 32];
    const unsigned int* dep_hctr = &g_hdone[set][ks * 32];

    // B gmem base (uint4 units): [(tileN*8+ks)][gk][row][4 uint4]
    const uint4* bslab = (const uint4*)g_bs + (long)(tileN * 8 + ks) * (9 * 512);
    const int bfrag = (wid * 32 + grp) * 4 + tig;

    // reduce constants: 1 fragment per warp, f = ks*4 + wid
    const int f   = ks * 4 + wid;
    const int fmt = f >> 4;
    const int fw  = (f >> 2) & 3;
    const int fnt = f & 3;
    const int fq  = fmt * 4 + fnt;
    const int r_m = m0 + fmt * 16 + (lane >> 2);
    const int r_n = n0 + fw * 32 + fnt * 8 + (lane & 3) * 2;
    const long r_pbase = (((long)(set * 64 + tileN * 8) * 4 + fw) * 8 + fq) * 32 + lane;
    const float r_b0 = bh[r_n];
    const float r_b1 = bh[r_n + 1];
    const int jj = r_n & 15;
    const int r_hoff = (r_m * 64 + (r_n >> 4)) * 16 +
                       ((jj < 8) ? (jj >> 1) * 4 : ((jj - 8) >> 1) * 4 + 1);

    float acc[2][4][4];
    uint4 u0, u1;
    uint4 bvP[4], bvQ[4];
    const uint32_t* hbase_cur;

    auto ldgB = [&](int gk, uint4* bv) {
        const uint4* src = bslab + gk * 512 + bfrag;
        #pragma unroll
        for (int nt = 0; nt < 4; nt++) bv[nt] = src[nt * 32];
    };
    auto compute16 = [&](const uint4* bv, const uint32_t* ab) {
        const uint32_t* ap = ab + grp * 16 + tig * 4;
        uint4 ra[2][2];
        #pragma unroll
        for (int mt = 0; mt < 2; mt++) {
            ra[mt][0] = *(const uint4*)(ap + mt * 256);
            ra[mt][1] = *(const uint4*)(ap + mt * 256 + 128);
        }
        #pragma unroll
        for (int nt = 0; nt < 4; nt++) {
            #pragma unroll
            for (int mt = 0; mt < 2; mt++) {
                mma16(acc[mt][nt], ra[mt][0].x, ra[mt][1].x, ra[mt][0].y, ra[mt][1].y,
                      bv[nt].x, bv[nt].y);
                mma16(acc[mt][nt], ra[mt][0].x, ra[mt][1].x, ra[mt][0].y, ra[mt][1].y,
                      bv[nt].z, bv[nt].w);
                mma16(acc[mt][nt], ra[mt][0].z, ra[mt][1].z, ra[mt][0].w, ra[mt][1].w,
                      bv[nt].x, bv[nt].y);
            }
        }
    };
    auto ldg_h = [&](int i) {
        const uint4* src = (const uint4*)hbase_cur +
            ((long)(m0 + arow) * 64 + ks * 8 + 2 * i) * 4 + aq;
        u0 = src[0];
        u1 = src[4];
    };
    auto sts_h = [&](int buf) {
        uint4* d = (uint4*)sA + buf * 256 + arow * 4 + aq;
        d[0]   = u0;
        d[128] = u1;
    };
    auto zero_acc = [&]() {
        #pragma unroll
        for (int mt = 0; mt < 2; mt++)
            #pragma unroll
            for (int nt = 0; nt < 4; nt++)
                #pragma unroll
                for (int c = 0; c < 4; c++)
                    acc[mt][nt][c] = 0.f;
    };
    // stage + compute the x chunk for timestep tt (h-independent work)
    auto x_chunk = [&](int tt) {
        ldgB(0, bvP);
        const uint4* src = (const uint4*)g_xs +
            (((long)(m0 + arow) * SEQ + tt) * 8 + ks) * 4 + aq;
        uint4 xv = src[0];
        ((uint4*)sA)[arow * 4 + aq] = xv;     // buf0 sub0
        __syncthreads();
        compute16(bvP, sA);
        ldgB(1, bvP);                          // pre-load first h group's B
    };

    // ---- prologue: x chunk for t = 0 ----
    zero_acc();
    x_chunk(0);

    for (int t = 0; t < SEQ; t++) {
        // ---- wait: producer tile `ks` finished reduce of step t-1 ----
        if (tid == 0) {
            const unsigned target = 8u * (unsigned)t;
            while (ld_acq(dep_hctr) < target) { }
        }
        __syncthreads();

        hbase_cur = g_hs[t & 1];

        // ---- 4 h chunks (k32), A double-buffered, B register-pipelined ----
        ldg_h(0);
        sts_h(1);
        __syncthreads();
        #pragma unroll 1
        for (int i = 0; i < 4; i++) {
            if (i < 3) ldg_h(i + 1);
            ldgB(2 + 2 * i, bvQ);
            const uint32_t* ab = sA + (((i + 1) & 1) * 1024);
            compute16(bvP, ab);
            if (i < 3) ldgB(3 + 2 * i, bvP);
            compute16(bvQ, ab + 512);
            if (i < 3) {
                sts_h(i & 1);
                __syncthreads();
            }
        }

        // ---- store partials (parity t) + release-signal ----
        {
            float4* pp = &g_part[t & 1][((long)(bid * 4 + wid) * 8) * 32 + lane];
            #pragma unroll
            for (int mt = 0; mt < 2; mt++)
                #pragma unroll
                for (int nt = 0; nt < 4; nt++) {
                    const int q = mt * 4 + nt;
                    pp[q * 32] = make_float4(acc[mt][nt][0], acc[mt][nt][1],
                                             acc[mt][nt][2], acc[mt][nt][3]);
                }
        }
        __syncthreads();
        if (tid == 0) sig_release(my_pctr);

        // ---- overlapped: x chunk of step t+1 (hides the pctr wait) ----
        zero_acc();
        if (t + 1 < SEQ) x_chunk(t + 1);   // safe: buf0's last reader barriered above

        // ---- wait: my tile's 8 partials stored ----
        if (tid == 0) {
            const unsigned target = 8u * (unsigned)(t + 1);
            while (ld_acq(my_pctr) < target) { }
        }
        __syncthreads();

        // ---- reduce: 1 fragment per warp ----
        {
            const float4* pbuf = g_part[t & 1];
            uint32_t* hdst = g_hs[(t + 1) & 1];
            float s0 = 0.f, s1 = 0.f, s2 = 0.f, s3 = 0.f;
            #pragma unroll
            for (int k2 = 0; k2 < 8; k2++) {
                float4 v = pbuf[r_pbase + (long)k2 * (4 * 8 * 32)];
                s0 += v.x; s1 += v.y; s2 += v.z; s3 += v.w;
            }
            const float t0 = my_tanh(s0 + r_b0);
            const float t1 = my_tanh(s1 + r_b1);
            const float t2 = my_tanh(s2 + r_b0);
            const float t3 = my_tanh(s3 + r_b1);
            const float f0 = bf16rt(t0), f1 = bf16rt(t1);
            const float f2 = bf16rt(t2), f3 = bf16rt(t3);
            hdst[r_hoff]            = pk2(t0, t1);
            hdst[r_hoff + 2]        = pk2(t0 - f0, t1 - f1);
            hdst[r_hoff + 8192]     = pk2(t2, t3);
            hdst[r_hoff + 8192 + 2] = pk2(t2 - f2, t3 - f3);
            if (t == SEQ - 1) {
                g_h[(long)r_m * HID + r_n]           = t0;
                g_h[(long)r_m * HID + r_n + 1]       = t1;
                g_h[(long)(r_m + 8) * HID + r_n]     = t2;
                g_h[(long)(r_m + 8) * HID + r_n + 1] = t3;
            }
        }
        __syncthreads();
        if (tid == 0) sig_release(my_hctr);
    }

    // ---- classifier + softmax: CTAs 0..255 handle one row each ----
    if (bid < BATCH) {
        const int row  = bid;
        const int setr = row >> 5;
        if (tid < 8) {
            const unsigned target = 8u * (unsigned)SEQ;
            while (ld_acq(&g_hdone[setr][tid * 32]) < target) { }
        }
        __syncthreads();

        float a[OUTC];
        #pragma unroll
        for (int o = 0; o < OUTC; o++) a[o] = 0.f;
        for (int k = tid; k < HID; k += NTH) {
            const float hv = g_h[(long)row * HID + k];
            const float* wr = Why + (long)k * OUTC;
            #pragma unroll
            for (int o = 0; o < OUTC; o++) a[o] += hv * wr[o];
        }
        #pragma unroll
        for (int o = 0; o < OUTC; o++)
            #pragma unroll
            for (int off = 16; off > 0; off >>= 1)
                a[o] += __shfl_down_sync(0xffffffffu, a[o], off);
        if (lane == 0) {
            #pragma unroll
            for (int o = 0; o < OUTC; o++) red[wid][o] = a[o];
        }
        __syncthreads();
        if (tid == 0) {
            float v[OUTC];
            float mx = -1e30f;
            #pragma unroll
            for (int o = 0; o < OUTC; o++) {
                v[o] = red[0][o] + red[1][o] + red[2][o] + red[3][o] + bo[o];
                mx = fmaxf(mx, v[o]);
            }
            float s = 0.f;
            #pragma unroll
            for (int o = 0; o < OUTC; o++) { v[o] = expf(v[o] - mx); s += v[o]; }
            const float inv = 1.0f / s;
            #pragma unroll
            for (int o = 0; o < OUTC; o++) out[row * OUTC + o] = v[o] * inv;
        }
    }
}

extern "C" void kernel_launch(void* const* d_in, const int* in_sizes, int n_in,
                              void* d_out, int out_size) {
    const float* x   = (const float*)d_in[0];
    const float* Whx = (const float*)d_in[1];
    const float* Whh = (const float*)d_in[2];
    const float* bh  = (const float*)d_in[3];
    const float* Why = (const float*)d_in[4];
    const float* bo  = (const float*)d_in[5];
    float* out = (float*)d_out;

    prep_kernel<<<1024, 256>>>(x, Whx, Whh);
    rnn_kernel<<<NCTA, NTH>>>(bh, Why, bo, out);
}